// round 3
// baseline (speedup 1.0000x reference)
#include <cuda_runtime.h>
#include <math.h>

#define HH 64
#define WW 64
#define BATCH 2
#define CCH 128
#define NPIX (BATCH*HH*WW)
#define KS 496   // 4 chunks * 124 (121 padded to 124 for float4 alignment)

// ---- scratch (static device allocations are allowed) ----
__device__ float g_scores[(size_t)NPIX * KS];   // [pixel][cc*124+p]
__device__ float g_wperm[KS * CCH];             // [cc*124+p][o], zero-padded rows
__device__ float g_m2[CCH * CCH];               // [c][o] : pos_enc folded through MLP

// ============================================================
// Kernel 0: prep — permute W rows (s=4p+cc -> s'=cc*124+p) and
// build M2[c][o] = sum_{s: g_s=c/32} pos_flat[s*32 + c%32] * W[s][o]
// ============================================================
__global__ __launch_bounds__(128) void prep_kernel(const float* __restrict__ W,
                                                   const float* __restrict__ pos) {
    int o = threadIdx.x;
    int bx = blockIdx.x;
    if (bx < KS) {
        int cc = bx / 124, p = bx - cc * 124;
        float v = 0.f;
        if (p < 121) v = W[(4 * p + cc) * CCH + o];
        g_wperm[bx * CCH + o] = v;
    } else {
        int c = bx - KS;           // 0..127
        int g = c >> 5, cm = c & 31;
        int s0 = 121 * g;
        float acc = 0.f;
        #pragma unroll 4
        for (int p = 0; p < 121; p++) {
            acc += pos[(s0 + p) * 32 + cm] * W[(s0 + p) * CCH + o];
        }
        g_m2[c * CCH + o] = acc;
    }
}

// ============================================================
// Kernel 1: scores. 4x4 pixel tile per CTA, halo (14x14) per 32-ch
// chunk in smem (stride 36 floats to avoid 32-bank aliasing).
// Thread = (pixel, lane); lane owns 16 consecutive p values, so its
// s-window is 64 wide => at most 2 q head-chunks, held in registers.
// scores[pixel][cc*124+p] = sum_d kv[pix+off(p)][cc*32+d]*q[pix][g*32+d]
// ============================================================
__global__ __launch_bounds__(128) void score_kernel(const float* __restrict__ q,
                                                    const float* __restrict__ kv) {
    __shared__ float s_kv[196 * 36];     // 14x14 positions, 32ch padded to 36
    __shared__ float s_q[16 * CCH];      // 16 pixels x 128 ch

    int tid = threadIdx.x;
    int b = blockIdx.z, h0 = blockIdx.y * 4, w0 = blockIdx.x * 4;

    // load q tile (coalesced float4)
    for (int idx = tid; idx < 512; idx += 128) {
        int pix = idx >> 5, d4 = idx & 31;
        int ph = pix >> 2, pw = pix & 3;
        const float4* src = (const float4*)(q + (size_t)((b * HH + h0 + ph) * WW + (w0 + pw)) * CCH);
        ((float4*)s_q)[pix * 32 + d4] = src[d4];
    }
    __syncthreads();

    int pix = tid >> 3, lane = tid & 7;
    int ph = pix >> 2, pw = pix & 3;
    int pixg = (b * HH + h0 + ph) * WW + (w0 + pw);

    int s_lo = 64 * lane, s_hi = 64 * lane + 63;
    int g_lo = (s_lo >= 121) + (s_lo >= 242) + (s_lo >= 363);
    int g_hi = (s_hi >= 121) + (s_hi >= 242) + (s_hi >= 363);

    float4 qA[8], qB[8];
    {
        const float4* sq4 = (const float4*)(s_q + pix * CCH);
        #pragma unroll
        for (int d4 = 0; d4 < 8; d4++) {
            qA[d4] = sq4[g_lo * 8 + d4];
            qB[d4] = sq4[g_hi * 8 + d4];
        }
    }

    for (int cc = 0; cc < 4; cc++) {
        __syncthreads();   // protect previous chunk's s_kv readers
        // load halo for this channel chunk
        for (int idx = tid; idx < 1568; idx += 128) {
            int pos = idx >> 3, d4 = idx & 7;
            int r = pos / 14, cpos = pos - r * 14;
            int y = h0 - 5 + r, x = w0 - 5 + cpos;
            float4 v = make_float4(0.f, 0.f, 0.f, 0.f);
            if ((unsigned)y < HH && (unsigned)x < WW)
                v = ((const float4*)(kv + (size_t)((b * HH + y) * WW + x) * CCH + cc * 32))[d4];
            *(float4*)&s_kv[pos * 36 + d4 * 4] = v;
        }
        __syncthreads();

        const float4* kv4 = (const float4*)s_kv;   // f4 stride 9 per position
        float* outp = g_scores + (size_t)pixg * KS + cc * 124 + lane * 16;
        int npi = (lane == 7) ? 12 : 16;
        for (int pi0 = 0; pi0 < npi; pi0 += 4) {
            float o4[4];
            #pragma unroll
            for (int u = 0; u < 4; u++) {
                int p = lane * 16 + pi0 + u;
                float acc = 0.f;
                if (p < 121) {
                    int i = p / 11;
                    int j = p - i * 11;
                    int s = 4 * p + cc;
                    int g = (s >= 121) + (s >= 242) + (s >= 363);
                    int base = ((ph + i) * 14 + (pw + j)) * 9;
                    if (g == g_lo) {
                        #pragma unroll
                        for (int d4 = 0; d4 < 8; d4++) {
                            float4 kvv = kv4[base + d4];
                            acc += kvv.x * qA[d4].x + kvv.y * qA[d4].y
                                 + kvv.z * qA[d4].z + kvv.w * qA[d4].w;
                        }
                    } else {
                        #pragma unroll
                        for (int d4 = 0; d4 < 8; d4++) {
                            float4 kvv = kv4[base + d4];
                            acc += kvv.x * qB[d4].x + kvv.y * qB[d4].y
                                 + kvv.z * qB[d4].z + kvv.w * qB[d4].w;
                        }
                    }
                }
                o4[u] = acc;
            }
            *(float4*)(outp + pi0) = make_float4(o4[0], o4[1], o4[2], o4[3]);
        }
    }
}

// ============================================================
// Kernel 2: fused GEMM (scores@Wperm + q@M2) + bias + gelu + residual + LN
// CTA tile: 64 M (pixels) x 128 N (outs). 128 threads, 8x8 thread tile.
// f32x2 packed FMA, register double-buffered gmem prefetch.
// ============================================================
__device__ __forceinline__ unsigned long long pk2(float x, float y) {
    unsigned long long r;
    asm("mov.b64 %0, {%1,%2};" : "=l"(r) : "f"(x), "f"(y));
    return r;
}
__device__ __forceinline__ void fma2(unsigned long long& d, unsigned long long a, unsigned long long b) {
    asm("fma.rn.f32x2 %0, %1, %2, %3;" : "=l"(d) : "l"(a), "l"(b), "l"(d));
}
__device__ __forceinline__ void upk2(unsigned long long v, float& x, float& y) {
    asm("mov.b64 {%0,%1}, %2;" : "=f"(x), "=f"(y) : "l"(v));
}

__global__ __launch_bounds__(128) void fused_gemm_kernel(
    const float* __restrict__ q,
    const float* __restrict__ bias,
    const float* __restrict__ lng,
    const float* __restrict__ lnb,
    float* __restrict__ out) {
    __shared__ float As[8 * 64];    // [k][m]
    __shared__ float Bs[8 * CCH];   // [k][n]

    int tid = threadIdx.x;
    int tx = tid & 15, ty = tid >> 4;
    int m0 = blockIdx.x * 64;

    unsigned long long acc[8][4];
    #pragma unroll
    for (int m = 0; m < 8; m++)
        #pragma unroll
        for (int n = 0; n < 4; n++) acc[m][n] = 0ULL;

    int pixL = tid >> 1, half = tid & 1;

    for (int phase = 0; phase < 2; phase++) {
        const float* A = (phase == 0) ? (g_scores + (size_t)m0 * KS) : (q + (size_t)m0 * CCH);
        int lda = (phase == 0) ? KS : CCH;
        const float* Bm = (phase == 0) ? g_wperm : g_m2;
        int nk = (phase == 0) ? (KS / 8) : (CCH / 8);

        // prefetch chunk 0
        float4 av = *(const float4*)&A[(size_t)pixL * lda + half * 4];
        float4 bv0 = *(const float4*)&Bm[(size_t)(tid >> 5) * CCH + (tid & 31) * 4];
        float4 bv1 = *(const float4*)&Bm[(size_t)(4 + (tid >> 5)) * CCH + (tid & 31) * 4];

        for (int kc = 0; kc < nk; kc++) {
            __syncthreads();
            // store staged tiles
            As[(half * 4 + 0) * 64 + pixL] = av.x;
            As[(half * 4 + 1) * 64 + pixL] = av.y;
            As[(half * 4 + 2) * 64 + pixL] = av.z;
            As[(half * 4 + 3) * 64 + pixL] = av.w;
            *(float4*)&Bs[(tid >> 5) * CCH + (tid & 31) * 4] = bv0;
            *(float4*)&Bs[(4 + (tid >> 5)) * CCH + (tid & 31) * 4] = bv1;
            __syncthreads();
            if (kc + 1 < nk) {
                int kn = (kc + 1) * 8;
                av = *(const float4*)&A[(size_t)pixL * lda + kn + half * 4];
                bv0 = *(const float4*)&Bm[(size_t)(kn + (tid >> 5)) * CCH + (tid & 31) * 4];
                bv1 = *(const float4*)&Bm[(size_t)(kn + 4 + (tid >> 5)) * CCH + (tid & 31) * 4];
            }
            #pragma unroll
            for (int k = 0; k < 8; k++) {
                float4 a0 = *(const float4*)&As[k * 64 + ty * 8];
                float4 a1 = *(const float4*)&As[k * 64 + ty * 8 + 4];
                float4 b0 = *(const float4*)&Bs[k * CCH + tx * 8];
                float4 b1 = *(const float4*)&Bs[k * CCH + tx * 8 + 4];
                unsigned long long bp[4];
                bp[0] = pk2(b0.x, b0.y); bp[1] = pk2(b0.z, b0.w);
                bp[2] = pk2(b1.x, b1.y); bp[3] = pk2(b1.z, b1.w);
                float am[8] = {a0.x, a0.y, a0.z, a0.w, a1.x, a1.y, a1.z, a1.w};
                #pragma unroll
                for (int m = 0; m < 8; m++) {
                    unsigned long long ad = pk2(am[m], am[m]);
                    #pragma unroll
                    for (int n = 0; n < 4; n++) fma2(acc[m][n], ad, bp[n]);
                }
            }
        }
        __syncthreads();
    }

    // ---- epilogue: bias + gelu(exact erf) + residual + layernorm ----
    float bi[8], gg[8], bb[8];
    {
        float4 t0 = *(const float4*)&bias[tx * 8];
        float4 t1 = *(const float4*)&bias[tx * 8 + 4];
        bi[0] = t0.x; bi[1] = t0.y; bi[2] = t0.z; bi[3] = t0.w;
        bi[4] = t1.x; bi[5] = t1.y; bi[6] = t1.z; bi[7] = t1.w;
        t0 = *(const float4*)&lng[tx * 8]; t1 = *(const float4*)&lng[tx * 8 + 4];
        gg[0] = t0.x; gg[1] = t0.y; gg[2] = t0.z; gg[3] = t0.w;
        gg[4] = t1.x; gg[5] = t1.y; gg[6] = t1.z; gg[7] = t1.w;
        t0 = *(const float4*)&lnb[tx * 8]; t1 = *(const float4*)&lnb[tx * 8 + 4];
        bb[0] = t0.x; bb[1] = t0.y; bb[2] = t0.z; bb[3] = t0.w;
        bb[4] = t1.x; bb[5] = t1.y; bb[6] = t1.z; bb[7] = t1.w;
    }
    const float inv128 = 1.0f / 128.0f;
    const float rsqrt2 = 0.70710678118654752f;

    #pragma unroll
    for (int mm = 0; mm < 8; mm++) {
        int pixg = m0 + ty * 8 + mm;
        float4 q0 = *(const float4*)&q[(size_t)pixg * CCH + tx * 8];
        float4 q1 = *(const float4*)&q[(size_t)pixg * CCH + tx * 8 + 4];
        float qv[8] = {q0.x, q0.y, q0.z, q0.w, q1.x, q1.y, q1.z, q1.w};
        float x[8];
        float s1 = 0.f, s2 = 0.f;
        #pragma unroll
        for (int n2 = 0; n2 < 4; n2++) {
            float lo, hi;
            upk2(acc[mm][n2], lo, hi);
            float p0 = lo + bi[n2 * 2 + 0];
            float p1 = hi + bi[n2 * 2 + 1];
            float e0 = 0.5f * p0 * (1.f + erff(p0 * rsqrt2));
            float e1 = 0.5f * p1 * (1.f + erff(p1 * rsqrt2));
            float x0 = e0 + qv[n2 * 2 + 0];
            float x1 = e1 + qv[n2 * 2 + 1];
            x[n2 * 2 + 0] = x0; x[n2 * 2 + 1] = x1;
            s1 += x0 + x1;
            s2 += x0 * x0 + x1 * x1;
        }
        // reduce across the 16 tx lanes (xor<=8 stays within the half-warp group)
        #pragma unroll
        for (int ofs = 8; ofs >= 1; ofs >>= 1) {
            s1 += __shfl_xor_sync(0xffffffffu, s1, ofs);
            s2 += __shfl_xor_sync(0xffffffffu, s2, ofs);
        }
        float mean = s1 * inv128;
        float var = s2 * inv128 - mean * mean;
        float rstd = rsqrtf(var + 1e-5f);
        float o[8];
        #pragma unroll
        for (int n = 0; n < 8; n++)
            o[n] = (x[n] - mean) * rstd * gg[n] + bb[n];
        *(float4*)&out[(size_t)pixg * CCH + tx * 8] = make_float4(o[0], o[1], o[2], o[3]);
        *(float4*)&out[(size_t)pixg * CCH + tx * 8 + 4] = make_float4(o[4], o[5], o[6], o[7]);
    }
}

// ============================================================
extern "C" void kernel_launch(void* const* d_in, const int* in_sizes, int n_in,
                              void* d_out, int out_size) {
    const float* q    = (const float*)d_in[0];
    const float* kv   = (const float*)d_in[1];
    const float* pos  = (const float*)d_in[2];
    const float* W    = (const float*)d_in[3];
    const float* bias = (const float*)d_in[4];
    const float* lng  = (const float*)d_in[5];
    const float* lnb  = (const float*)d_in[6];
    float* out = (float*)d_out;

    prep_kernel<<<KS + CCH, 128>>>(W, pos);
    score_kernel<<<dim3(WW / 4, HH / 4, BATCH), 128>>>(q, kv);
    fused_gemm_kernel<<<NPIX / 64, 128>>>(q, bias, lng, lnb, out);
}